// round 7
// baseline (speedup 1.0000x reference)
#include <cuda_runtime.h>
#include <math.h>
#include <stdint.h>

#define NN 100000
#define DD 128
#define NE 1600000

#define HSTRIDE 132
#define MLP_THREADS 128          // 4 warps; each warp owns 32 rows
#define ROWS_PER_BLOCK 128
#define N_CHUNKS 24              // 12 layer-0 (384 k) + 12 inner (3 layers x 128 k)

// Scratch (allocation-free rule: __device__ globals)
__device__ int   g_cnt[2 * NN];       // [0,NN): in-degree, [NN,2NN): out-degree
__device__ int   g_cursors[2];
__device__ int   g_off_in[NN];
__device__ int   g_off_out[NN];
__device__ int   g_cur_in[NN];
__device__ int   g_cur_out[NN];
__device__ int2  g_lst_in[NE];        // {src, w-bits} keyed by dst
__device__ int2  g_lst_out[NE];       // {dst, w-bits} keyed by src
__device__ uint4 g_wfrag[N_CHUNKS * 4 * 8 * 32];   // frag-major tf32 weights

// ---------------------------------------------------------------------------
__device__ __forceinline__ uint32_t f2tf32(float v) {
    uint32_t r;
    asm("cvt.rna.tf32.f32 %0, %1;" : "=r"(r) : "f"(v));
    return r;
}

__device__ __forceinline__ float fast_tanh(float x) {
    float ax = fabsf(x);
    float t = __expf(-2.f * ax);
    float r = (1.f - t) * __frcp_rn(1.f + t);
    return copysignf(r, x);
}

// ---------------------------------------------------------------------------
// W0 [384,128] + W [3,128,128] -> fragment-major tf32 (see round-6 layout).
// ---------------------------------------------------------------------------
__global__ void wfrag_kernel(const float* __restrict__ W0,
                             const float* __restrict__ W,
                             uint4* __restrict__ WF) {
    int idx = blockIdx.x * blockDim.x + threadIdx.x;
    if (idx >= N_CHUNKS * 4 * 8 * 32) return;
    int lane = idx & 31;
    int q = (idx >> 5) & 7;
    int ks = (idx >> 8) & 3;
    int chunk = idx >> 10;
    int t4 = lane & 3, g = lane >> 2;
    int n0 = q * 16 + g;
    int n1 = n0 + 8;

    float w00, w01, w10, w11;
    if (chunk < 12) {
        int r = chunk * 32 + ks * 8 + t4;
        w00 = __ldg(&W0[(size_t)r * 128 + n0]);
        w01 = __ldg(&W0[(size_t)(r + 4) * 128 + n0]);
        w10 = __ldg(&W0[(size_t)r * 128 + n1]);
        w11 = __ldg(&W0[(size_t)(r + 4) * 128 + n1]);
    } else {
        int c2 = chunk - 12;
        int l = c2 >> 2;
        int r = (c2 & 3) * 32 + ks * 8 + t4;
        const float* Wl = W + (size_t)l * 128 * 128;
        w00 = __ldg(&Wl[(size_t)r * 128 + n0]);
        w01 = __ldg(&Wl[(size_t)(r + 4) * 128 + n0]);
        w10 = __ldg(&Wl[(size_t)r * 128 + n1]);
        w11 = __ldg(&Wl[(size_t)(r + 4) * 128 + n1]);
    }
    uint4 o;
    o.x = f2tf32(w00); o.y = f2tf32(w01);
    o.z = f2tf32(w10); o.w = f2tf32(w11);
    WF[idx] = o;
}

// ---------------------------------------------------------------------------
// Histogram of edge endpoints (8 edges per thread)
// ---------------------------------------------------------------------------
__global__ void hist_kernel(const int* __restrict__ ei, int* __restrict__ cnt) {
    int i = blockIdx.x * blockDim.x + threadIdx.x;
    if (i >= NE / 8) return;
    int4 s0 = __ldg((const int4*)ei + 2 * i);
    int4 s1 = __ldg((const int4*)ei + 2 * i + 1);
    int4 t0 = __ldg((const int4*)(ei + NE) + 2 * i);
    int4 t1 = __ldg((const int4*)(ei + NE) + 2 * i + 1);
    atomicAdd(&cnt[t0.x], 1); atomicAdd(&cnt[t0.y], 1);
    atomicAdd(&cnt[t0.z], 1); atomicAdd(&cnt[t0.w], 1);
    atomicAdd(&cnt[t1.x], 1); atomicAdd(&cnt[t1.y], 1);
    atomicAdd(&cnt[t1.z], 1); atomicAdd(&cnt[t1.w], 1);
    atomicAdd(&cnt[NN + s0.x], 1); atomicAdd(&cnt[NN + s0.y], 1);
    atomicAdd(&cnt[NN + s0.z], 1); atomicAdd(&cnt[NN + s0.w], 1);
    atomicAdd(&cnt[NN + s1.x], 1); atomicAdd(&cnt[NN + s1.y], 1);
    atomicAdd(&cnt[NN + s1.z], 1); atomicAdd(&cnt[NN + s1.w], 1);
}

// ---------------------------------------------------------------------------
// Parallel segment allocation (offsets unordered): warp-aggregated cursor.
// ---------------------------------------------------------------------------
__global__ void alloc_kernel(const int* __restrict__ cnt,
                             int* __restrict__ offin, int* __restrict__ curin,
                             int* __restrict__ offout, int* __restrict__ curout,
                             int* __restrict__ cursors) {
    int i = blockIdx.x * blockDim.x + threadIdx.x;
    if (i >= 2 * NN) return;
    int lane = threadIdx.x & 31;
    int c = cnt[i];
    int inc = c;
#pragma unroll
    for (int o = 1; o < 32; o <<= 1) {
        int v = __shfl_up_sync(0xFFFFFFFFu, inc, o);
        if (lane >= o) inc += v;
    }
    int tot = __shfl_sync(0xFFFFFFFFu, inc, 31);
    int ex = inc - c;
    int half = (i < NN) ? 0 : 1;
    int base = 0;
    if (lane == 0) base = atomicAdd(&cursors[half], tot);
    base = __shfl_sync(0xFFFFFFFFu, base, 0);
    int off = base + ex;
    if (half == 0) { offin[i] = off; curin[i] = off; }
    else           { offout[i - NN] = off; curout[i - NN] = off; }
}

// ---------------------------------------------------------------------------
// Fill CSR edge lists: 8 edges/thread, all atomics issued before stores (MLP)
// ---------------------------------------------------------------------------
__global__ void fill_kernel(const int* __restrict__ ei, const float* __restrict__ e,
                            int* __restrict__ curin, int* __restrict__ curout,
                            int2* __restrict__ lin, int2* __restrict__ lout) {
    int i = blockIdx.x * blockDim.x + threadIdx.x;
    if (i >= NE / 8) return;
    int4 s0 = __ldg((const int4*)ei + 2 * i);
    int4 s1 = __ldg((const int4*)ei + 2 * i + 1);
    int4 t0 = __ldg((const int4*)(ei + NE) + 2 * i);
    int4 t1 = __ldg((const int4*)(ei + NE) + 2 * i + 1);
    float4 w0 = __ldg((const float4*)e + 2 * i);
    float4 w1 = __ldg((const float4*)e + 2 * i + 1);
    int ss[8] = {s0.x, s0.y, s0.z, s0.w, s1.x, s1.y, s1.z, s1.w};
    int tt[8] = {t0.x, t0.y, t0.z, t0.w, t1.x, t1.y, t1.z, t1.w};
    float ww[8] = {w0.x, w0.y, w0.z, w0.w, w1.x, w1.y, w1.z, w1.w};

    int pin[8], pout[8];
#pragma unroll
    for (int u = 0; u < 8; u++) pin[u] = atomicAdd(&curin[tt[u]], 1);
#pragma unroll
    for (int u = 0; u < 8; u++) pout[u] = atomicAdd(&curout[ss[u]], 1);
#pragma unroll
    for (int u = 0; u < 8; u++) lin[pin[u]] = make_int2(ss[u], __float_as_int(ww[u]));
#pragma unroll
    for (int u = 0; u < 8; u++) lout[pout[u]] = make_int2(tt[u], __float_as_int(ww[u]));
}

// ---------------------------------------------------------------------------
// Fused gather + 4-layer MLP, sync-free across warps.
// Warp owns 32 rows. Layer-0: gather mi (then mo) for those 32 nodes into the
// per-warp smem slab, run MMA chunks from the slab; x chunks read global
// directly. Inner layers as round 6.
// ---------------------------------------------------------------------------
#define MMA4(cj, A0r, A1r, A2r, A3r, B0r, B1r)                                   \
    asm volatile(                                                                \
        "mma.sync.aligned.m16n8k8.row.col.f32.tf32.tf32.f32 "                    \
        "{%0,%1,%2,%3}, {%4,%5,%6,%7}, {%8,%9}, {%0,%1,%2,%3};"                  \
        : "+f"(cj[0]), "+f"(cj[1]), "+f"(cj[2]), "+f"(cj[3])                     \
        : "r"(A0r), "r"(A1r), "r"(A2r), "r"(A3r), "r"(B0r), "r"(B1r))

__global__ __launch_bounds__(MLP_THREADS, 2) void mlp_fused(
    const float* __restrict__ x,
    const int* __restrict__ cnt,
    const int* __restrict__ offin, const int2* __restrict__ lin,
    const int* __restrict__ offout, const int2* __restrict__ lout,
    const uint4* __restrict__ WF,
    const float* __restrict__ b0v, const float* __restrict__ g0v,
    const float* __restrict__ be0v,
    const float* __restrict__ bv, const float* __restrict__ gv,
    const float* __restrict__ bev,
    float* __restrict__ out)
{
    extern __shared__ uint32_t smem[];
    const int tid = threadIdx.x;
    const int lane = tid & 31;
    const int wid = tid >> 5;
    const int g = lane >> 2;
    const int t4 = lane & 3;
    const int row0 = blockIdx.x * ROWS_PER_BLOCK + wid * 32;

    uint32_t* Hw = smem + wid * 32 * HSTRIDE;   // per-warp slab [32][HSTRIDE]
    float* Hf = (float*)Hw;

    float c[2][16][4];
#pragma unroll
    for (int t = 0; t < 2; t++)
#pragma unroll
        for (int j = 0; j < 16; j++)
#pragma unroll
            for (int q = 0; q < 4; q++) c[t][j][q] = 0.f;

    int r00 = row0 + g;
    int r10 = row0 + 16 + g;
    int cr00 = r00 < NN ? r00 : 0;
    int cr01 = (r00 + 8) < NN ? (r00 + 8) : 0;
    int cr10 = r10 < NN ? r10 : 0;
    int cr11 = (r10 + 8) < NN ? (r10 + 8) : 0;

    // ---------------- Layer 0: m = 0 (mi), 1 (mo), 2 (x) ----------------
#pragma unroll 1
    for (int m = 0; m < 3; m++) {
        if (m < 2) {
            // Gather 32 nodes' weighted neighbor sums into slab (fp32)
            const int* off = (m == 0) ? offin : offout;
            const int2* lst = (m == 0) ? lin : lout;
            const int cofs = (m == 0) ? 0 : NN;
            __syncwarp();   // prior slab reads complete
#pragma unroll 1
            for (int r = 0; r < 32; r++) {
                int node = row0 + r;
                float4 acc = make_float4(0.f, 0.f, 0.f, 0.f);
                if (node < NN) {
                    int beg = off[node];
                    int end = beg + cnt[cofs + node];
                    int j = beg;
                    for (; j + 4 <= end; j += 4) {
                        int2 p0 = __ldg(&lst[j]);
                        int2 p1 = __ldg(&lst[j + 1]);
                        int2 p2 = __ldg(&lst[j + 2]);
                        int2 p3 = __ldg(&lst[j + 3]);
                        float4 v0 = __ldg((const float4*)(x + (size_t)p0.x * DD) + lane);
                        float4 v1 = __ldg((const float4*)(x + (size_t)p1.x * DD) + lane);
                        float4 v2 = __ldg((const float4*)(x + (size_t)p2.x * DD) + lane);
                        float4 v3 = __ldg((const float4*)(x + (size_t)p3.x * DD) + lane);
                        float a0 = __int_as_float(p0.y), a1 = __int_as_float(p1.y);
                        float a2 = __int_as_float(p2.y), a3 = __int_as_float(p3.y);
                        acc.x = fmaf(a0, v0.x, acc.x); acc.y = fmaf(a0, v0.y, acc.y);
                        acc.z = fmaf(a0, v0.z, acc.z); acc.w = fmaf(a0, v0.w, acc.w);
                        acc.x = fmaf(a1, v1.x, acc.x); acc.y = fmaf(a1, v1.y, acc.y);
                        acc.z = fmaf(a1, v1.z, acc.z); acc.w = fmaf(a1, v1.w, acc.w);
                        acc.x = fmaf(a2, v2.x, acc.x); acc.y = fmaf(a2, v2.y, acc.y);
                        acc.z = fmaf(a2, v2.z, acc.z); acc.w = fmaf(a2, v2.w, acc.w);
                        acc.x = fmaf(a3, v3.x, acc.x); acc.y = fmaf(a3, v3.y, acc.y);
                        acc.z = fmaf(a3, v3.z, acc.z); acc.w = fmaf(a3, v3.w, acc.w);
                    }
                    for (; j < end; j++) {
                        int2 p0 = __ldg(&lst[j]);
                        float4 v0 = __ldg((const float4*)(x + (size_t)p0.x * DD) + lane);
                        float a0 = __int_as_float(p0.y);
                        acc.x = fmaf(a0, v0.x, acc.x); acc.y = fmaf(a0, v0.y, acc.y);
                        acc.z = fmaf(a0, v0.z, acc.z); acc.w = fmaf(a0, v0.w, acc.w);
                    }
                }
                ((float4*)(Hf + r * HSTRIDE))[lane] = acc;
            }
            __syncwarp();
        }

#pragma unroll 1
        for (int kc = 0; kc < 4; kc++) {
            int chunk = m * 4 + kc;
#pragma unroll
            for (int ks = 0; ks < 4; ks++) {
                int kidx = kc * 32 + ks * 8 + t4;
                uint32_t a0[4], a1[4];
                if (m < 2) {
                    a0[0] = f2tf32(Hf[(g) * HSTRIDE + kidx]);
                    a0[1] = f2tf32(Hf[(g + 8) * HSTRIDE + kidx]);
                    a0[2] = f2tf32(Hf[(g) * HSTRIDE + kidx + 4]);
                    a0[3] = f2tf32(Hf[(g + 8) * HSTRIDE + kidx + 4]);
                    a1[0] = f2tf32(Hf[(16 + g) * HSTRIDE + kidx]);
                    a1[1] = f2tf32(Hf[(24 + g) * HSTRIDE + kidx]);
                    a1[2] = f2tf32(Hf[(16 + g) * HSTRIDE + kidx + 4]);
                    a1[3] = f2tf32(Hf[(24 + g) * HSTRIDE + kidx + 4]);
                } else {
                    a0[0] = f2tf32(__ldg(x + (size_t)cr00 * DD + kidx));
                    a0[1] = f2tf32(__ldg(x + (size_t)cr01 * DD + kidx));
                    a0[2] = f2tf32(__ldg(x + (size_t)cr00 * DD + kidx + 4));
                    a0[3] = f2tf32(__ldg(x + (size_t)cr01 * DD + kidx + 4));
                    a1[0] = f2tf32(__ldg(x + (size_t)cr10 * DD + kidx));
                    a1[1] = f2tf32(__ldg(x + (size_t)cr11 * DD + kidx));
                    a1[2] = f2tf32(__ldg(x + (size_t)cr10 * DD + kidx + 4));
                    a1[3] = f2tf32(__ldg(x + (size_t)cr11 * DD + kidx + 4));
                }
                const uint4* wfk = WF + ((size_t)(chunk * 4 + ks) << 8);
#pragma unroll
                for (int q = 0; q < 8; q++) {
                    uint4 bb = __ldg(&wfk[(q << 5) + lane]);
                    MMA4(c[0][2 * q],     a0[0], a0[1], a0[2], a0[3], bb.x, bb.y);
                    MMA4(c[0][2 * q + 1], a0[0], a0[1], a0[2], a0[3], bb.z, bb.w);
                    MMA4(c[1][2 * q],     a1[0], a1[1], a1[2], a1[3], bb.x, bb.y);
                    MMA4(c[1][2 * q + 1], a1[0], a1[1], a1[2], a1[3], bb.z, bb.w);
                }
            }
        }
    }

    // ---------------- 4 epilogues + 3 inner layers ----------------
#pragma unroll 1
    for (int l = 0; l < 4; l++) {
        const float* bias  = (l == 0) ? b0v  : bv  + (l - 1) * 128;
        const float* gamma = (l == 0) ? g0v  : gv  + (l - 1) * 128;
        const float* beta  = (l == 0) ? be0v : bev + (l - 1) * 128;

        float s[2][2], qq[2][2];
#pragma unroll
        for (int t = 0; t < 2; t++) { s[t][0]=s[t][1]=qq[t][0]=qq[t][1]=0.f; }

#pragma unroll
        for (int j = 0; j < 16; j++) {
            int col = j * 8 + 2 * t4;
            float2 bb = __ldg((const float2*)(bias + col));
#pragma unroll
            for (int t = 0; t < 2; t++) {
                c[t][j][0] += bb.x; c[t][j][1] += bb.y;
                c[t][j][2] += bb.x; c[t][j][3] += bb.y;
                s[t][0]  += c[t][j][0] + c[t][j][1];
                qq[t][0] += c[t][j][0] * c[t][j][0] + c[t][j][1] * c[t][j][1];
                s[t][1]  += c[t][j][2] + c[t][j][3];
                qq[t][1] += c[t][j][2] * c[t][j][2] + c[t][j][3] * c[t][j][3];
            }
        }
#pragma unroll
        for (int o = 1; o <= 2; o <<= 1) {
#pragma unroll
            for (int t = 0; t < 2; t++) {
                s[t][0]  += __shfl_xor_sync(0xFFFFFFFFu, s[t][0], o);
                qq[t][0] += __shfl_xor_sync(0xFFFFFFFFu, qq[t][0], o);
                s[t][1]  += __shfl_xor_sync(0xFFFFFFFFu, s[t][1], o);
                qq[t][1] += __shfl_xor_sync(0xFFFFFFFFu, qq[t][1], o);
            }
        }
        float mean[2][2], rstd[2][2];
#pragma unroll
        for (int t = 0; t < 2; t++)
#pragma unroll
            for (int h = 0; h < 2; h++) {
                mean[t][h] = s[t][h] * (1.f / 128.f);
                rstd[t][h] = rsqrtf(qq[t][h] * (1.f / 128.f) - mean[t][h] * mean[t][h] + 1e-5f);
            }

        if (l == 3) {
#pragma unroll
            for (int j = 0; j < 16; j++) {
                int col = j * 8 + 2 * t4;
                float2 gg = __ldg((const float2*)(gamma + col));
                float2 ee = __ldg((const float2*)(beta + col));
#pragma unroll
                for (int t = 0; t < 2; t++) {
                    int ra = row0 + t * 16 + g;
                    int rb = ra + 8;
                    if (ra < NN) {
                        float2 o1;
                        o1.x = fast_tanh((c[t][j][0] - mean[t][0]) * rstd[t][0] * gg.x + ee.x);
                        o1.y = fast_tanh((c[t][j][1] - mean[t][0]) * rstd[t][0] * gg.y + ee.y);
                        *(float2*)(out + (size_t)ra * DD + col) = o1;
                    }
                    if (rb < NN) {
                        float2 o2;
                        o2.x = fast_tanh((c[t][j][2] - mean[t][1]) * rstd[t][1] * gg.x + ee.x);
                        o2.y = fast_tanh((c[t][j][3] - mean[t][1]) * rstd[t][1] * gg.y + ee.y);
                        *(float2*)(out + (size_t)rb * DD + col) = o2;
                    }
                }
            }
            break;
        }

        // Write h (tf32 bits) into per-warp smem slab
        __syncwarp();
#pragma unroll
        for (int j = 0; j < 16; j++) {
            int col = j * 8 + 2 * t4;
            float2 gg = __ldg((const float2*)(gamma + col));
            float2 ee = __ldg((const float2*)(beta + col));
#pragma unroll
            for (int t = 0; t < 2; t++) {
                float h00 = fast_tanh((c[t][j][0] - mean[t][0]) * rstd[t][0] * gg.x + ee.x);
                float h01 = fast_tanh((c[t][j][1] - mean[t][0]) * rstd[t][0] * gg.y + ee.y);
                float h10 = fast_tanh((c[t][j][2] - mean[t][1]) * rstd[t][1] * gg.x + ee.x);
                float h11 = fast_tanh((c[t][j][3] - mean[t][1]) * rstd[t][1] * gg.y + ee.y);
                uint32_t* p1 = Hw + (t * 16 + g) * HSTRIDE + col;
                uint32_t* p2 = Hw + (t * 16 + g + 8) * HSTRIDE + col;
                p1[0] = f2tf32(h00); p1[1] = f2tf32(h01);
                p2[0] = f2tf32(h10); p2[1] = f2tf32(h11);
                c[t][j][0] = 0.f; c[t][j][1] = 0.f;
                c[t][j][2] = 0.f; c[t][j][3] = 0.f;
            }
        }
        __syncwarp();

        // Next layer GEMM: h (in Hw, tf32 bits) @ W[l], K = 128
#pragma unroll
        for (int kc = 0; kc < 4; kc++) {
            int chunk = 12 + l * 4 + kc;
#pragma unroll
            for (int ks = 0; ks < 4; ks++) {
                int kidx = kc * 32 + ks * 8 + t4;
                uint32_t a0[4], a1[4];
                a0[0] = Hw[(g) * HSTRIDE + kidx];
                a0[1] = Hw[(g + 8) * HSTRIDE + kidx];
                a0[2] = Hw[(g) * HSTRIDE + kidx + 4];
                a0[3] = Hw[(g + 8) * HSTRIDE + kidx + 4];
                a1[0] = Hw[(16 + g) * HSTRIDE + kidx];
                a1[1] = Hw[(24 + g) * HSTRIDE + kidx];
                a1[2] = Hw[(16 + g) * HSTRIDE + kidx + 4];
                a1[3] = Hw[(24 + g) * HSTRIDE + kidx + 4];
                const uint4* wfk = WF + ((size_t)(chunk * 4 + ks) << 8);
#pragma unroll
                for (int q = 0; q < 8; q++) {
                    uint4 bb = __ldg(&wfk[(q << 5) + lane]);
                    MMA4(c[0][2 * q],     a0[0], a0[1], a0[2], a0[3], bb.x, bb.y);
                    MMA4(c[0][2 * q + 1], a0[0], a0[1], a0[2], a0[3], bb.z, bb.w);
                    MMA4(c[1][2 * q],     a1[0], a1[1], a1[2], a1[3], bb.x, bb.y);
                    MMA4(c[1][2 * q + 1], a1[0], a1[1], a1[2], a1[3], bb.z, bb.w);
                }
            }
        }
    }
}

// ---------------------------------------------------------------------------
extern "C" void kernel_launch(void* const* d_in, const int* in_sizes, int n_in,
                              void* d_out, int out_size) {
    const float* x   = (const float*)d_in[0];
    const float* e   = (const float*)d_in[1];
    const int*   ei  = (const int*)d_in[2];
    const float* W0  = (const float*)d_in[3];
    const float* b0  = (const float*)d_in[4];
    const float* g0  = (const float*)d_in[5];
    const float* be0 = (const float*)d_in[6];
    const float* W   = (const float*)d_in[7];
    const float* b   = (const float*)d_in[8];
    const float* g   = (const float*)d_in[9];
    const float* be  = (const float*)d_in[10];
    float* out = (float*)d_out;

    int *cnt, *cursors, *offin, *offout, *curin, *curout;
    int2 *lin, *lout;
    uint4* wf;
    cudaGetSymbolAddress((void**)&cnt, g_cnt);
    cudaGetSymbolAddress((void**)&cursors, g_cursors);
    cudaGetSymbolAddress((void**)&offin, g_off_in);
    cudaGetSymbolAddress((void**)&offout, g_off_out);
    cudaGetSymbolAddress((void**)&curin, g_cur_in);
    cudaGetSymbolAddress((void**)&curout, g_cur_out);
    cudaGetSymbolAddress((void**)&lin, g_lst_in);
    cudaGetSymbolAddress((void**)&lout, g_lst_out);
    cudaGetSymbolAddress((void**)&wf, g_wfrag);

    const int smem_bytes = 4 * 32 * HSTRIDE * 4;   // 4 warps x 32 rows x 132 words
    cudaFuncSetAttribute(mlp_fused,
                         cudaFuncAttributeMaxDynamicSharedMemorySize,
                         smem_bytes);

    cudaMemsetAsync(cnt, 0, 2 * NN * sizeof(int));
    cudaMemsetAsync(cursors, 0, 2 * sizeof(int));

    wfrag_kernel<<<(N_CHUNKS * 1024 + 255) / 256, 256>>>(W0, W, wf);
    hist_kernel<<<(NE / 8 + 255) / 256, 256>>>(ei, cnt);
    alloc_kernel<<<(2 * NN + 255) / 256, 256>>>(cnt, offin, curin, offout, curout, cursors);
    fill_kernel<<<(NE / 8 + 255) / 256, 256>>>(ei, e, curin, curout, lin, lout);

    const int gblocks = (NN + ROWS_PER_BLOCK - 1) / ROWS_PER_BLOCK;  // 782
    mlp_fused<<<gblocks, MLP_THREADS, smem_bytes>>>(
        x, cnt, offin, lin, offout, lout, wf,
        b0, g0, be0, b, g, be, out);
}

// round 8
// speedup vs baseline: 1.6945x; 1.6945x over previous
#include <cuda_runtime.h>
#include <cuda_fp16.h>
#include <math.h>
#include <stdint.h>

#define NN 100000
#define DD 128
#define NE 1600000

#define MLP_THREADS 128          // 4 warps; each warp owns 32 rows
#define ROWS_PER_BLOCK 128
#define N_CHUNKS 24              // 12 layer-0 (384 k) + 12 inner (3 x 128 k)
#define HS16 68                  // H slab row stride in uint32 (half2) units

// Scratch (allocation-free rule: __device__ globals)
__device__ uint32_t g_xh[(size_t)NN * 64];    // x as half2 pairs
__device__ uint32_t g_mih[(size_t)NN * 64];   // mi as half2
__device__ uint32_t g_moh[(size_t)NN * 64];   // mo as half2

__device__ int   g_cnt[2 * NN];
__device__ int   g_cursors[2];
__device__ int   g_off_in[NN];
__device__ int   g_off_out[NN];
__device__ int   g_cur_in[NN];
__device__ int   g_cur_out[NN];
__device__ int2  g_lst_in[NE];
__device__ int2  g_lst_out[NE];
__device__ uint4 g_wfrag[N_CHUNKS * 2 * 8 * 32];   // fp16 frag-major weights

// ---------------------------------------------------------------------------
__device__ __forceinline__ float fast_tanh(float x) {
    float ax = fabsf(x);
    float t = __expf(-2.f * ax);
    float r = (1.f - t) * __frcp_rn(1.f + t);
    return copysignf(r, x);
}

__device__ __forceinline__ uint32_t pack_h2(float a, float b) {
    __half2 h = __floats2half2_rn(a, b);
    return *(uint32_t*)&h;
}

// ---------------------------------------------------------------------------
// Convert x fp32 -> fp16x2 buffer. Thread handles 4 elements.
// ---------------------------------------------------------------------------
__global__ void xconv_kernel(const float* __restrict__ x, uint32_t* __restrict__ xh) {
    int i = blockIdx.x * blockDim.x + threadIdx.x;
    if (i >= NN * 32) return;   // NN*128/4
    float4 v = __ldg((const float4*)x + i);
    uint2 o;
    o.x = pack_h2(v.x, v.y);
    o.y = pack_h2(v.z, v.w);
    ((uint2*)xh)[i] = o;
}

// ---------------------------------------------------------------------------
// W0 [384,128] + W [3,128,128] -> fp16 fragment-major for m16n8k16:
// uint4 idx = ((chunk*2 + s)*8 + q)*32 + lane holds
//  { b0(j=2q), b1(j=2q), b0(j=2q+1), b1(j=2q+1) } where
//  b0(j) = half2( W[k0][n], W[k0+1][n] ), b1(j) = half2( W[k0+8][n], W[k0+9][n] ),
//  k0 = kbase + s*16 + 2*t4, n = j*8 + g.
// ---------------------------------------------------------------------------
__global__ void wfrag_kernel(const float* __restrict__ W0,
                             const float* __restrict__ W,
                             uint4* __restrict__ WF) {
    int idx = blockIdx.x * blockDim.x + threadIdx.x;
    if (idx >= N_CHUNKS * 2 * 8 * 32) return;
    int lane = idx & 31;
    int q = (idx >> 5) & 7;
    int s = (idx >> 8) & 1;
    int chunk = idx >> 9;
    int t4 = lane & 3, g = lane >> 2;

    const float* Wsrc;
    int kbase;
    if (chunk < 12) {
        Wsrc = W0;
        kbase = chunk * 32;
    } else {
        int c2 = chunk - 12;
        Wsrc = W + (size_t)(c2 >> 2) * 128 * 128;
        kbase = (c2 & 3) * 32;
    }
    int k0 = kbase + s * 16 + 2 * t4;
    int n0 = (2 * q) * 8 + g;
    int n1 = n0 + 8;

    uint4 o;
    o.x = pack_h2(__ldg(&Wsrc[(size_t)k0 * 128 + n0]),       __ldg(&Wsrc[(size_t)(k0 + 1) * 128 + n0]));
    o.y = pack_h2(__ldg(&Wsrc[(size_t)(k0 + 8) * 128 + n0]), __ldg(&Wsrc[(size_t)(k0 + 9) * 128 + n0]));
    o.z = pack_h2(__ldg(&Wsrc[(size_t)k0 * 128 + n1]),       __ldg(&Wsrc[(size_t)(k0 + 1) * 128 + n1]));
    o.w = pack_h2(__ldg(&Wsrc[(size_t)(k0 + 8) * 128 + n1]), __ldg(&Wsrc[(size_t)(k0 + 9) * 128 + n1]));
    WF[idx] = o;
}

// ---------------------------------------------------------------------------
// Histogram (8 edges/thread)
// ---------------------------------------------------------------------------
__global__ void hist_kernel(const int* __restrict__ ei, int* __restrict__ cnt) {
    int i = blockIdx.x * blockDim.x + threadIdx.x;
    if (i >= NE / 8) return;
    int4 s0 = __ldg((const int4*)ei + 2 * i);
    int4 s1 = __ldg((const int4*)ei + 2 * i + 1);
    int4 t0 = __ldg((const int4*)(ei + NE) + 2 * i);
    int4 t1 = __ldg((const int4*)(ei + NE) + 2 * i + 1);
    atomicAdd(&cnt[t0.x], 1); atomicAdd(&cnt[t0.y], 1);
    atomicAdd(&cnt[t0.z], 1); atomicAdd(&cnt[t0.w], 1);
    atomicAdd(&cnt[t1.x], 1); atomicAdd(&cnt[t1.y], 1);
    atomicAdd(&cnt[t1.z], 1); atomicAdd(&cnt[t1.w], 1);
    atomicAdd(&cnt[NN + s0.x], 1); atomicAdd(&cnt[NN + s0.y], 1);
    atomicAdd(&cnt[NN + s0.z], 1); atomicAdd(&cnt[NN + s0.w], 1);
    atomicAdd(&cnt[NN + s1.x], 1); atomicAdd(&cnt[NN + s1.y], 1);
    atomicAdd(&cnt[NN + s1.z], 1); atomicAdd(&cnt[NN + s1.w], 1);
}

// ---------------------------------------------------------------------------
// Parallel segment allocation (offsets unordered)
// ---------------------------------------------------------------------------
__global__ void alloc_kernel(const int* __restrict__ cnt,
                             int* __restrict__ offin, int* __restrict__ curin,
                             int* __restrict__ offout, int* __restrict__ curout,
                             int* __restrict__ cursors) {
    int i = blockIdx.x * blockDim.x + threadIdx.x;
    if (i >= 2 * NN) return;
    int lane = threadIdx.x & 31;
    int c = cnt[i];
    int inc = c;
#pragma unroll
    for (int o = 1; o < 32; o <<= 1) {
        int v = __shfl_up_sync(0xFFFFFFFFu, inc, o);
        if (lane >= o) inc += v;
    }
    int tot = __shfl_sync(0xFFFFFFFFu, inc, 31);
    int ex = inc - c;
    int half = (i < NN) ? 0 : 1;
    int base = 0;
    if (lane == 0) base = atomicAdd(&cursors[half], tot);
    base = __shfl_sync(0xFFFFFFFFu, base, 0);
    int off = base + ex;
    if (half == 0) { offin[i] = off; curin[i] = off; }
    else           { offout[i - NN] = off; curout[i - NN] = off; }
}

// ---------------------------------------------------------------------------
// Fill CSR lists (8 edges/thread, atomics batched before stores)
// ---------------------------------------------------------------------------
__global__ void fill_kernel(const int* __restrict__ ei, const float* __restrict__ e,
                            int* __restrict__ curin, int* __restrict__ curout,
                            int2* __restrict__ lin, int2* __restrict__ lout) {
    int i = blockIdx.x * blockDim.x + threadIdx.x;
    if (i >= NE / 8) return;
    int4 s0 = __ldg((const int4*)ei + 2 * i);
    int4 s1 = __ldg((const int4*)ei + 2 * i + 1);
    int4 t0 = __ldg((const int4*)(ei + NE) + 2 * i);
    int4 t1 = __ldg((const int4*)(ei + NE) + 2 * i + 1);
    float4 w0 = __ldg((const float4*)e + 2 * i);
    float4 w1 = __ldg((const float4*)e + 2 * i + 1);
    int ss[8] = {s0.x, s0.y, s0.z, s0.w, s1.x, s1.y, s1.z, s1.w};
    int tt[8] = {t0.x, t0.y, t0.z, t0.w, t1.x, t1.y, t1.z, t1.w};
    float ww[8] = {w0.x, w0.y, w0.z, w0.w, w1.x, w1.y, w1.z, w1.w};

    int pin[8], pout[8];
#pragma unroll
    for (int u = 0; u < 8; u++) pin[u] = atomicAdd(&curin[tt[u]], 1);
#pragma unroll
    for (int u = 0; u < 8; u++) pout[u] = atomicAdd(&curout[ss[u]], 1);
#pragma unroll
    for (int u = 0; u < 8; u++) lin[pin[u]] = make_int2(ss[u], __float_as_int(ww[u]));
#pragma unroll
    for (int u = 0; u < 8; u++) lout[pout[u]] = make_int2(tt[u], __float_as_int(ww[u]));
}

// ---------------------------------------------------------------------------
// Gather (fp16): one warp per (node, dir). Lane owns 4 fp16 columns.
// Reads xh rows (uint2 = 4 fp16), accumulates fp32, writes fp16x2.
// ---------------------------------------------------------------------------
__global__ __launch_bounds__(256) void gather_kernel(
    const uint32_t* __restrict__ xh, const int* __restrict__ cnt,
    const int* __restrict__ offin, const int2* __restrict__ lin,
    const int* __restrict__ offout, const int2* __restrict__ lout,
    uint32_t* __restrict__ mih, uint32_t* __restrict__ moh) {
    int wg = (blockIdx.x * blockDim.x + threadIdx.x) >> 5;
    int lane = threadIdx.x & 31;
    if (wg >= 2 * NN) return;

    const int* off;
    const int2* lst;
    uint32_t* dst;
    int node, cofs;
    if (wg < NN) { node = wg; off = offin; lst = lin; dst = mih; cofs = 0; }
    else         { node = wg - NN; off = offout; lst = lout; dst = moh; cofs = NN; }

    int beg = off[node];
    int end = beg + cnt[cofs + node];

    float2 acc0 = make_float2(0.f, 0.f);
    float2 acc1 = make_float2(0.f, 0.f);

    int j = beg;
    for (; j + 8 <= end; j += 8) {
        int2 p[8];
#pragma unroll
        for (int u = 0; u < 8; u++) p[u] = __ldg(&lst[j + u]);
        uint2 v[8];
#pragma unroll
        for (int u = 0; u < 8; u++)
            v[u] = __ldg((const uint2*)(xh + (size_t)p[u].x * 64) + lane);
#pragma unroll
        for (int u = 0; u < 8; u++) {
            float w = __int_as_float(p[u].y);
            float2 f0 = __half22float2(*(__half2*)&v[u].x);
            float2 f1 = __half22float2(*(__half2*)&v[u].y);
            acc0.x = fmaf(w, f0.x, acc0.x); acc0.y = fmaf(w, f0.y, acc0.y);
            acc1.x = fmaf(w, f1.x, acc1.x); acc1.y = fmaf(w, f1.y, acc1.y);
        }
    }
    for (; j < end; j++) {
        int2 p0 = __ldg(&lst[j]);
        uint2 v0 = __ldg((const uint2*)(xh + (size_t)p0.x * 64) + lane);
        float w = __int_as_float(p0.y);
        float2 f0 = __half22float2(*(__half2*)&v0.x);
        float2 f1 = __half22float2(*(__half2*)&v0.y);
        acc0.x = fmaf(w, f0.x, acc0.x); acc0.y = fmaf(w, f0.y, acc0.y);
        acc1.x = fmaf(w, f1.x, acc1.x); acc1.y = fmaf(w, f1.y, acc1.y);
    }

    uint2 o;
    o.x = pack_h2(acc0.x, acc0.y);
    o.y = pack_h2(acc1.x, acc1.y);
    ((uint2*)(dst + (size_t)node * 64))[lane] = o;
}

// ---------------------------------------------------------------------------
// Fused 4-layer MLP, fp16 m16n8k16, sync-free across warps.
// Warp owns 32 rows (two m16 tiles). A operands: global fp16 (layer 0) or
// per-warp smem slab (inner layers). B: frag-major global (L1-shared).
// ---------------------------------------------------------------------------
#define MMA16(cj, A0r, A1r, A2r, A3r, B0r, B1r)                                  \
    asm volatile(                                                                \
        "mma.sync.aligned.m16n8k16.row.col.f32.f16.f16.f32 "                     \
        "{%0,%1,%2,%3}, {%4,%5,%6,%7}, {%8,%9}, {%0,%1,%2,%3};"                  \
        : "+f"(cj[0]), "+f"(cj[1]), "+f"(cj[2]), "+f"(cj[3])                     \
        : "r"(A0r), "r"(A1r), "r"(A2r), "r"(A3r), "r"(B0r), "r"(B1r))

__global__ __launch_bounds__(MLP_THREADS, 2) void mlp_fused(
    const uint32_t* __restrict__ A0h, const uint32_t* __restrict__ A1h,
    const uint32_t* __restrict__ A2h,
    const uint4* __restrict__ WF,
    const float* __restrict__ b0v, const float* __restrict__ g0v,
    const float* __restrict__ be0v,
    const float* __restrict__ bv, const float* __restrict__ gv,
    const float* __restrict__ bev,
    float* __restrict__ out)
{
    extern __shared__ uint32_t smem[];
    const int tid = threadIdx.x;
    const int lane = tid & 31;
    const int wid = tid >> 5;
    const int g = lane >> 2;
    const int t4 = lane & 3;
    const int row0 = blockIdx.x * ROWS_PER_BLOCK + wid * 32;

    uint32_t* Hw = smem + wid * 32 * HS16;   // per-warp slab [32][HS16] half2

    float c[2][16][4];
#pragma unroll
    for (int t = 0; t < 2; t++)
#pragma unroll
        for (int j = 0; j < 16; j++)
#pragma unroll
            for (int q = 0; q < 4; q++) c[t][j][q] = 0.f;

    int r00 = row0 + g;
    int r10 = row0 + 16 + g;
    size_t cr00 = (size_t)(r00 < NN ? r00 : 0) * 64;
    size_t cr01 = (size_t)((r00 + 8) < NN ? (r00 + 8) : 0) * 64;
    size_t cr10 = (size_t)(r10 < NN ? r10 : 0) * 64;
    size_t cr11 = (size_t)((r10 + 8) < NN ? (r10 + 8) : 0) * 64;

    // ---------------- Layer 0: K = 384 over {mih, moh, xh} ----------------
    const uint32_t* Ap[3] = {A0h, A1h, A2h};
#pragma unroll 1
    for (int m = 0; m < 3; m++) {
        const uint32_t* A = Ap[m];
#pragma unroll
        for (int kc = 0; kc < 4; kc++) {
            int chunk = m * 4 + kc;
#pragma unroll
            for (int s = 0; s < 2; s++) {
                int kidx = kc * 16 + s * 8 + t4;       // uint32 (half2) index
                uint32_t a0[4], a1[4];
                a0[0] = __ldg(A + cr00 + kidx);
                a0[1] = __ldg(A + cr01 + kidx);
                a0[2] = __ldg(A + cr00 + kidx + 4);
                a0[3] = __ldg(A + cr01 + kidx + 4);
                a1[0] = __ldg(A + cr10 + kidx);
                a1[1] = __ldg(A + cr11 + kidx);
                a1[2] = __ldg(A + cr10 + kidx + 4);
                a1[3] = __ldg(A + cr11 + kidx + 4);
                const uint4* wfk = WF + ((size_t)(chunk * 2 + s) << 8);
#pragma unroll
                for (int q = 0; q < 8; q++) {
                    uint4 bb = __ldg(&wfk[(q << 5) + lane]);
                    MMA16(c[0][2 * q],     a0[0], a0[1], a0[2], a0[3], bb.x, bb.y);
                    MMA16(c[0][2 * q + 1], a0[0], a0[1], a0[2], a0[3], bb.z, bb.w);
                    MMA16(c[1][2 * q],     a1[0], a1[1], a1[2], a1[3], bb.x, bb.y);
                    MMA16(c[1][2 * q + 1], a1[0], a1[1], a1[2], a1[3], bb.z, bb.w);
                }
            }
        }
    }

    // ---------------- 4 epilogues + 3 inner layers ----------------
#pragma unroll 1
    for (int l = 0; l < 4; l++) {
        const float* bias  = (l == 0) ? b0v  : bv  + (l - 1) * 128;
        const float* gamma = (l == 0) ? g0v  : gv  + (l - 1) * 128;
        const float* beta  = (l == 0) ? be0v : bev + (l - 1) * 128;

        float s[2][2], qq[2][2];
#pragma unroll
        for (int t = 0; t < 2; t++) { s[t][0]=s[t][1]=qq[t][0]=qq[t][1]=0.f; }

#pragma unroll
        for (int j = 0; j < 16; j++) {
            int col = j * 8 + 2 * t4;
            float2 bb = __ldg((const float2*)(bias + col));
#pragma unroll
            for (int t = 0; t < 2; t++) {
                c[t][j][0] += bb.x; c[t][j][1] += bb.y;
                c[t][j][2] += bb.x; c[t][j][3] += bb.y;
                s[t][0]  += c[t][j][0] + c[t][j][1];
                qq[t][0] += c[t][j][0] * c[t][j][0] + c[t][j][1] * c[t][j][1];
                s[t][1]  += c[t][j][2] + c[t][j][3];
                qq[t][1] += c[t][j][2] * c[t][j][2] + c[t][j][3] * c[t][j][3];
            }
        }
#pragma unroll
        for (int o = 1; o <= 2; o <<= 1) {
#pragma unroll
            for (int t = 0; t < 2; t++) {
                s[t][0]  += __shfl_xor_sync(0xFFFFFFFFu, s[t][0], o);
                qq[t][0] += __shfl_xor_sync(0xFFFFFFFFu, qq[t][0], o);
                s[t][1]  += __shfl_xor_sync(0xFFFFFFFFu, s[t][1], o);
                qq[t][1] += __shfl_xor_sync(0xFFFFFFFFu, qq[t][1], o);
            }
        }
        float mean[2][2], rstd[2][2];
#pragma unroll
        for (int t = 0; t < 2; t++)
#pragma unroll
            for (int h = 0; h < 2; h++) {
                mean[t][h] = s[t][h] * (1.f / 128.f);
                rstd[t][h] = rsqrtf(qq[t][h] * (1.f / 128.f) - mean[t][h] * mean[t][h] + 1e-5f);
            }

        if (l == 3) {
#pragma unroll
            for (int j = 0; j < 16; j++) {
                int col = j * 8 + 2 * t4;
                float2 gg = __ldg((const float2*)(gamma + col));
                float2 ee = __ldg((const float2*)(beta + col));
#pragma unroll
                for (int t = 0; t < 2; t++) {
                    int ra = row0 + t * 16 + g;
                    int rb = ra + 8;
                    if (ra < NN) {
                        float2 o1;
                        o1.x = fast_tanh((c[t][j][0] - mean[t][0]) * rstd[t][0] * gg.x + ee.x);
                        o1.y = fast_tanh((c[t][j][1] - mean[t][0]) * rstd[t][0] * gg.y + ee.y);
                        *(float2*)(out + (size_t)ra * DD + col) = o1;
                    }
                    if (rb < NN) {
                        float2 o2;
                        o2.x = fast_tanh((c[t][j][2] - mean[t][1]) * rstd[t][1] * gg.x + ee.x);
                        o2.y = fast_tanh((c[t][j][3] - mean[t][1]) * rstd[t][1] * gg.y + ee.y);
                        *(float2*)(out + (size_t)rb * DD + col) = o2;
                    }
                }
            }
            break;
        }

        // Write h (half2) into per-warp smem slab. Col pair (2t4, 2t4+1) is one uint32.
        __syncwarp();
#pragma unroll
        for (int j = 0; j < 16; j++) {
            int col = j * 8 + 2 * t4;
            float2 gg = __ldg((const float2*)(gamma + col));
            float2 ee = __ldg((const float2*)(beta + col));
            int ci = j * 4 + t4;    // uint32 column index
#pragma unroll
            for (int t = 0; t < 2; t++) {
                float h00 = fast_tanh((c[t][j][0] - mean[t][0]) * rstd[t][0] * gg.x + ee.x);
                float h01 = fast_tanh((c[t][j][1] - mean[t][0]) * rstd[t][0] * gg.y + ee.y);
                float h10 = fast_tanh((c[t][j][2] - mean[t][1]) * rstd[t][1] * gg.x + ee.x);
                float h11 = fast_tanh((c[t][j][3] - mean[t][1]) * rstd[t][1] * gg.y + ee.y);
                Hw[(t * 16 + g) * HS16 + ci]     = pack_h2(h00, h01);
                Hw[(t * 16 + g + 8) * HS16 + ci] = pack_h2(h10, h11);
                c[t][j][0] = 0.f; c[t][j][1] = 0.f;
                c[t][j][2] = 0.f; c[t][j][3] = 0.f;
            }
        }
        __syncwarp();

        // Next layer GEMM: h (in Hw) @ W[l], K = 128
#pragma unroll
        for (int kc = 0; kc < 4; kc++) {
            int chunk = 12 + l * 4 + kc;
#pragma unroll
            for (int s = 0; s < 2; s++) {
                int kidx = kc * 16 + s * 8 + t4;
                uint32_t a0[4], a1[4];
                a0[0] = Hw[(g) * HS16 + kidx];
                a0[1] = Hw[(g + 8) * HS16 + kidx];
                a0[2] = Hw[(g) * HS16 + kidx + 4];
                a0[3] = Hw[(g + 8) * HS16 + kidx + 4];
                a1[0] = Hw[(16 + g) * HS16 + kidx];
                a1[1] = Hw[(24 + g) * HS16 + kidx];
                a1[2] = Hw[(16 + g) * HS16 + kidx + 4];
                a1[3] = Hw[(24 + g) * HS16 + kidx + 4];
                const uint4* wfk = WF + ((size_t)(chunk * 2 + s) << 8);
#pragma unroll
                for (int q = 0; q < 8; q++) {
                    uint4 bb = __ldg(&wfk[(q << 5) + lane]);
                    MMA16(c[0][2 * q],     a0[0], a0[1], a0[2], a0[3], bb.x, bb.y);
                    MMA16(c[0][2 * q + 1], a0[0], a0[1], a0[2], a0[3], bb.z, bb.w);
                    MMA16(c[1][2 * q],     a1[0], a1[1], a1[2], a1[3], bb.x, bb.y);
                    MMA16(c[1][2 * q + 1], a1[0], a1[1], a1[2], a1[3], bb.z, bb.w);
                }
            }
        }
    }
}

// ---------------------------------------------------------------------------
extern "C" void kernel_launch(void* const* d_in, const int* in_sizes, int n_in,
                              void* d_out, int out_size) {
    const float* x   = (const float*)d_in[0];
    const float* e   = (const float*)d_in[1];
    const int*   ei  = (const int*)d_in[2];
    const float* W0  = (const float*)d_in[3];
    const float* b0  = (const float*)d_in[4];
    const float* g0  = (const float*)d_in[5];
    const float* be0 = (const float*)d_in[6];
    const float* W   = (const float*)d_in[7];
    const float* b   = (const float*)d_in[8];
    const float* g   = (const float*)d_in[9];
    const float* be  = (const float*)d_in[10];
    float* out = (float*)d_out;

    uint32_t *xh, *mih, *moh;
    int *cnt, *cursors, *offin, *offout, *curin, *curout;
    int2 *lin, *lout;
    uint4* wf;
    cudaGetSymbolAddress((void**)&xh, g_xh);
    cudaGetSymbolAddress((void**)&mih, g_mih);
    cudaGetSymbolAddress((void**)&moh, g_moh);
    cudaGetSymbolAddress((void**)&cnt, g_cnt);
    cudaGetSymbolAddress((void**)&cursors, g_cursors);
    cudaGetSymbolAddress((void**)&offin, g_off_in);
    cudaGetSymbolAddress((void**)&offout, g_off_out);
    cudaGetSymbolAddress((void**)&curin, g_cur_in);
    cudaGetSymbolAddress((void**)&curout, g_cur_out);
    cudaGetSymbolAddress((void**)&lin, g_lst_in);
    cudaGetSymbolAddress((void**)&lout, g_lst_out);
    cudaGetSymbolAddress((void**)&wf, g_wfrag);

    const int smem_bytes = 4 * 32 * HS16 * 4;   // 4 warps x 32 rows x 68 words
    cudaFuncSetAttribute(mlp_fused,
                         cudaFuncAttributeMaxDynamicSharedMemorySize,
                         smem_bytes);

    cudaMemsetAsync(cnt, 0, 2 * NN * sizeof(int));
    cudaMemsetAsync(cursors, 0, 2 * sizeof(int));

    xconv_kernel<<<(NN * 32 + 255) / 256, 256>>>(x, xh);
    wfrag_kernel<<<(N_CHUNKS * 512 + 255) / 256, 256>>>(W0, W, wf);
    hist_kernel<<<(NE / 8 + 255) / 256, 256>>>(ei, cnt);
    alloc_kernel<<<(2 * NN + 255) / 256, 256>>>(cnt, offin, curin, offout, curout, cursors);
    fill_kernel<<<(NE / 8 + 255) / 256, 256>>>(ei, e, curin, curout, lin, lout);

    {
        long long warps = 2LL * NN;
        int blocks = (int)((warps * 32 + 255) / 256);
        gather_kernel<<<blocks, 256>>>(xh, cnt, offin, lin, offout, lout, mih, moh);
    }

    const int gblocks = (NN + ROWS_PER_BLOCK - 1) / ROWS_PER_BLOCK;  // 782
    mlp_fused<<<gblocks, MLP_THREADS, smem_bytes>>>(
        mih, moh, xh, wf, b0, g0, be0, b, g, be, out);
}